// round 4
// baseline (speedup 1.0000x reference)
#include <cuda_runtime.h>
#include <cuda_bf16.h>
#include <math.h>

// Problem constants (fixed by the reference)
#define B_SZ 2
#define SEQ 2048
#define DMODEL 1536
#define NHEADS 24
#define KVHEADS 6
#define HDIM 64
#define ROT 32
#define ROWS (B_SZ * SEQ)          // 4096
#define KVDIM (KVHEADS * HDIM)     // 384

// Scratch buffers (no allocation allowed -> device globals)
__device__ float g_Q[ROWS * DMODEL];
__device__ float g_K[ROWS * KVDIM];
__device__ float g_V[ROWS * KVDIM];
__device__ float g_A[ROWS * DMODEL];

// ---------------------------------------------------------------------------
// Packed f32x2 helpers (FFMA2 path — only reachable via PTX fma.rn.f32x2)
// ---------------------------------------------------------------------------
typedef unsigned long long u64;

__device__ __forceinline__ u64 ffma2(u64 a, u64 b, u64 c) {
    u64 d;
    asm("fma.rn.f32x2 %0, %1, %2, %3;" : "=l"(d) : "l"(a), "l"(b), "l"(c));
    return d;
}
__device__ __forceinline__ u64 fmul2(u64 a, u64 b) {
    u64 d;
    asm("mul.rn.f32x2 %0, %1, %2;" : "=l"(d) : "l"(a), "l"(b));
    return d;
}
__device__ __forceinline__ u64 pack2(float lo, float hi) {
    u64 d;
    asm("mov.b64 %0, {%1, %2};" : "=l"(d) : "f"(lo), "f"(hi));
    return d;
}
__device__ __forceinline__ float2 unpack2(u64 v) {
    float lo, hi;
    asm("mov.b64 {%0, %1}, %2;" : "=f"(lo), "=f"(hi) : "l"(v));
    return make_float2(lo, hi);
}

// ---------------------------------------------------------------------------
// Generic tiled GEMM: C[M,N] = A[M,K] @ B[K,N]   (row-major everywhere)
// Tile: 64x64x16, 256 threads, 4x4 register micro-tile per thread,
// inner product via packed FFMA2 (2 fp32 FMAs per issue).
// EPILOGUE: C = A@B + bias[n] + residual[m*N+n]
// ---------------------------------------------------------------------------
template<bool EPILOGUE>
__global__ __launch_bounds__(256)
void gemm64(const float* __restrict__ A, const float* __restrict__ Bm,
            float* __restrict__ C, int M, int N, int K,
            const float* __restrict__ bias, const float* __restrict__ residual)
{
    __shared__ float As[16][64];
    __shared__ float Bs[16][64];

    const int t  = threadIdx.x;
    const int tx = t & 15;          // 0..15
    const int ty = t >> 4;          // 0..15
    const int m0 = blockIdx.y * 64;
    const int n0 = blockIdx.x * 64;

    u64 acc2[4][2];
#pragma unroll
    for (int i = 0; i < 4; ++i) { acc2[i][0] = 0ull; acc2[i][1] = 0ull; }

    const int ar = t >> 2;           // 0..63  A row within tile
    const int ac = (t & 3) << 2;     // 0,4,8,12
    const int br = t >> 4;           // 0..15  B row within tile
    const int bc = (t & 15) << 2;    // 0..60

    for (int k0 = 0; k0 < K; k0 += 16) {
        float4 a4 = *(const float4*)(A + (size_t)(m0 + ar) * K + k0 + ac);
        As[ac + 0][ar] = a4.x;
        As[ac + 1][ar] = a4.y;
        As[ac + 2][ar] = a4.z;
        As[ac + 3][ar] = a4.w;
        *(float4*)&Bs[br][bc] = *(const float4*)(Bm + (size_t)(k0 + br) * N + n0 + bc);
        __syncthreads();

#pragma unroll
        for (int kk = 0; kk < 16; ++kk) {
            float4 av = *(const float4*)&As[kk][ty << 2];
            ulonglong2 bv = *(const ulonglong2*)&Bs[kk][tx << 2];
            u64 a0 = pack2(av.x, av.x);
            u64 a1 = pack2(av.y, av.y);
            u64 a2 = pack2(av.z, av.z);
            u64 a3 = pack2(av.w, av.w);
            acc2[0][0] = ffma2(a0, bv.x, acc2[0][0]);
            acc2[0][1] = ffma2(a0, bv.y, acc2[0][1]);
            acc2[1][0] = ffma2(a1, bv.x, acc2[1][0]);
            acc2[1][1] = ffma2(a1, bv.y, acc2[1][1]);
            acc2[2][0] = ffma2(a2, bv.x, acc2[2][0]);
            acc2[2][1] = ffma2(a2, bv.y, acc2[2][1]);
            acc2[3][0] = ffma2(a3, bv.x, acc2[3][0]);
            acc2[3][1] = ffma2(a3, bv.y, acc2[3][1]);
        }
        __syncthreads();
    }

#pragma unroll
    for (int i = 0; i < 4; ++i) {
        int m = m0 + (ty << 2) + i;
        size_t rowoff = (size_t)m * N + n0 + (tx << 2);
        float2 lo = unpack2(acc2[i][0]);
        float2 hi = unpack2(acc2[i][1]);
        float4 v = make_float4(lo.x, lo.y, hi.x, hi.y);
        if (EPILOGUE) {
            int n = n0 + (tx << 2);
            const float4 r4 = *(const float4*)(residual + rowoff);
            v.x += bias[n + 0] + r4.x;
            v.y += bias[n + 1] + r4.y;
            v.z += bias[n + 2] + r4.z;
            v.w += bias[n + 3] + r4.w;
        }
        *(float4*)(C + rowoff) = v;
    }
}

// ---------------------------------------------------------------------------
// Partial RoPE in place. X: [ROWS, nheads*64].  cos/sin: [SEQ, 32] with
// cos[:, d] == cos[:, d+16].  Each thread handles one (row, head, d<16) pair.
// ---------------------------------------------------------------------------
__global__ void rope_kernel(float* __restrict__ X,
                            const float* __restrict__ cosb,
                            const float* __restrict__ sinb,
                            int nheads, int total)
{
    int idx = blockIdx.x * blockDim.x + threadIdx.x;
    if (idx >= total) return;
    int d   = idx & 15;
    int tmp = idx >> 4;
    int h   = tmp % nheads;
    int row = tmp / nheads;
    int s   = row & (SEQ - 1);

    float c  = cosb[s * ROT + d];
    float sn = sinb[s * ROT + d];
    float* p = X + (size_t)row * (nheads * HDIM) + h * HDIM;
    float xr = p[d];
    float xi = p[d + 16];
    p[d]      = xr * c - xi * sn;
    p[d + 16] = xi * c + xr * sn;
}

// ---------------------------------------------------------------------------
// Flash-style attention.  grid = (SEQ/128, B*NHEADS), 128 threads.
// Each thread owns one q row (packed, 32 u64) and its packed accumulator.
// KV processed in 64-row chunks staged in dynamic smem; chunk scores go
// through padded smem so exp() uses a stable per-row chunk max.
// All inner products and axpy loops use packed FFMA2.
// ---------------------------------------------------------------------------
__global__ __launch_bounds__(128)
void attn_kernel(const float* __restrict__ Q, const float* __restrict__ K,
                 const float* __restrict__ V, float* __restrict__ O)
{
    extern __shared__ float sm[];
    float* Ks = sm;            // 64*64
    float* Vs = sm + 4096;     // 64*64
    float* Ss = sm + 8192;     // 128*65 (padded: stride 65 -> conflict-free)

    const int tid = threadIdx.x;
    const int bh  = blockIdx.y;
    const int b   = bh / NHEADS;
    const int h   = bh % NHEADS;
    const int kvh = h / (NHEADS / KVHEADS);   // h/4

    const int qrow = b * SEQ + blockIdx.x * 128 + tid;
    const float* qp = Q + (size_t)qrow * DMODEL + h * HDIM;

    u64 q2[32];
    {
        const ulonglong2* qp2 = (const ulonglong2*)qp;
#pragma unroll
        for (int i = 0; i < 16; ++i) {
            ulonglong2 v = qp2[i];
            q2[2 * i]     = v.x;
            q2[2 * i + 1] = v.y;
        }
    }

    u64 acc2[32];
#pragma unroll
    for (int p = 0; p < 32; ++p) acc2[p] = 0ull;
    float m = -1e30f;
    float l = 0.f;

    const size_t kvbase = (size_t)b * SEQ * KVDIM + kvh * HDIM;

    for (int j0 = 0; j0 < SEQ; j0 += 64) {
        // cooperative load of K,V chunk: 64 rows x 64 cols each
        for (int i = tid; i < 64 * 16; i += 128) {
            int r  = i >> 4;
            int c4 = (i & 15) << 2;
            size_t goff = kvbase + (size_t)(j0 + r) * KVDIM + c4;
            *(float4*)&Ks[r * 64 + c4] = *(const float4*)(K + goff);
            *(float4*)&Vs[r * 64 + c4] = *(const float4*)(V + goff);
        }
        __syncthreads();

        // pass A: scores for this chunk + chunk max (packed dot products)
        float cmax = -1e30f;
        float* srow = Ss + tid * 65;
        for (int j = 0; j < 64; ++j) {
            const ulonglong2* kr = (const ulonglong2*)(Ks + j * 64);
            u64 s0 = 0ull, s1 = 0ull;
#pragma unroll
            for (int d8 = 0; d8 < 16; ++d8) {
                ulonglong2 kv = kr[d8];
                s0 = ffma2(q2[2 * d8],     kv.x, s0);
                s1 = ffma2(q2[2 * d8 + 1], kv.y, s1);
            }
            float2 f0 = unpack2(s0);
            float2 f1 = unpack2(s1);
            float s = ((f0.x + f1.x) + (f0.y + f1.y)) * 0.125f;  // 1/sqrt(64)
            cmax = fmaxf(cmax, s);
            srow[j] = s;
        }

        // online-softmax rescale (packed)
        float mnew = fmaxf(m, cmax);
        float corr = __expf(m - mnew);
        l *= corr;
        u64 corr2 = pack2(corr, corr);
#pragma unroll
        for (int p = 0; p < 32; ++p) acc2[p] = fmul2(acc2[p], corr2);

        // pass B: accumulate p * V (packed axpy)
        for (int j = 0; j < 64; ++j) {
            float p = __expf(srow[j] - mnew);
            l += p;
            u64 p2 = pack2(p, p);
            const ulonglong2* vr = (const ulonglong2*)(Vs + j * 64);
#pragma unroll
            for (int d8 = 0; d8 < 16; ++d8) {
                ulonglong2 vv = vr[d8];
                acc2[2 * d8]     = ffma2(p2, vv.x, acc2[2 * d8]);
                acc2[2 * d8 + 1] = ffma2(p2, vv.y, acc2[2 * d8 + 1]);
            }
        }
        m = mnew;
        __syncthreads();
    }

    float inv_l = 1.f / l;
    u64 il2 = pack2(inv_l, inv_l);
    float* op = O + (size_t)qrow * DMODEL + h * HDIM;
#pragma unroll
    for (int d8 = 0; d8 < 16; ++d8) {
        float2 a = unpack2(fmul2(acc2[2 * d8],     il2));
        float2 c = unpack2(fmul2(acc2[2 * d8 + 1], il2));
        float4 v = make_float4(a.x, a.y, c.x, c.y);
        *(float4*)(op + d8 * 4) = v;
    }
}

// ---------------------------------------------------------------------------
extern "C" void kernel_launch(void* const* d_in, const int* in_sizes, int n_in,
                              void* d_out, int out_size)
{
    const float* hidden = (const float*)d_in[0];
    const float* cosb   = (const float*)d_in[1];
    const float* sinb   = (const float*)d_in[2];
    const float* Wq     = (const float*)d_in[3];
    const float* Wk     = (const float*)d_in[4];
    const float* Wv     = (const float*)d_in[5];
    const float* Wo     = (const float*)d_in[6];
    const float* bo     = (const float*)d_in[7];
    float* out          = (float*)d_out;

    float *Qp, *Kp, *Vp, *Ap;
    cudaGetSymbolAddress((void**)&Qp, g_Q);
    cudaGetSymbolAddress((void**)&Kp, g_K);
    cudaGetSymbolAddress((void**)&Vp, g_V);
    cudaGetSymbolAddress((void**)&Ap, g_A);

    // QKV projections
    gemm64<false><<<dim3(DMODEL / 64, ROWS / 64), 256>>>(hidden, Wq, Qp,
        ROWS, DMODEL, DMODEL, nullptr, nullptr);
    gemm64<false><<<dim3(KVDIM / 64, ROWS / 64), 256>>>(hidden, Wk, Kp,
        ROWS, KVDIM, DMODEL, nullptr, nullptr);
    gemm64<false><<<dim3(KVDIM / 64, ROWS / 64), 256>>>(hidden, Wv, Vp,
        ROWS, KVDIM, DMODEL, nullptr, nullptr);

    // RoPE (partial, rot=32) on Q and K
    {
        int totq = ROWS * NHEADS * 16;
        rope_kernel<<<(totq + 255) / 256, 256>>>(Qp, cosb, sinb, NHEADS, totq);
        int totk = ROWS * KVHEADS * 16;
        rope_kernel<<<(totk + 255) / 256, 256>>>(Kp, cosb, sinb, KVHEADS, totk);
    }

    // Attention
    {
        const int smem = (4096 + 4096 + 128 * 65) * sizeof(float);  // 66048 B
        cudaFuncSetAttribute(attn_kernel,
                             cudaFuncAttributeMaxDynamicSharedMemorySize, smem);
        attn_kernel<<<dim3(SEQ / 128, B_SZ * NHEADS), 128, smem>>>(Qp, Kp, Vp, Ap);
    }

    // Output projection + bias + residual
    gemm64<true><<<dim3(DMODEL / 64, ROWS / 64), 256>>>(Ap, Wo, out,
        ROWS, DMODEL, DMODEL, bo, hidden);
}

// round 8
// speedup vs baseline: 1.3715x; 1.3715x over previous
#include <cuda_runtime.h>
#include <cuda_bf16.h>
#include <cstdint>
#include <math.h>

// Problem constants
#define B_SZ 2
#define SEQ 2048
#define DMODEL 1536
#define NHEADS 24
#define KVHEADS 6
#define HDIM 64
#define ROT 32
#define ROWS (B_SZ * SEQ)          // 4096
#define KVDIM (KVHEADS * HDIM)     // 384
#define K3 (3 * DMODEL)            // 4608  (split-K: [hi | lo | hi])

// Scratch (device globals; no allocation allowed)
__device__ float g_Q[ROWS * DMODEL];
__device__ float g_K[ROWS * KVDIM];
__device__ float g_V[ROWS * KVDIM];
__device__ float g_A[ROWS * DMODEL];
__device__ __nv_bfloat16 g_A3[(size_t)ROWS * K3];     // split activations
__device__ __nv_bfloat16 g_Bq[(size_t)DMODEL * K3];   // split+transposed weights
__device__ __nv_bfloat16 g_Bk[(size_t)KVDIM * K3];
__device__ __nv_bfloat16 g_Bv[(size_t)KVDIM * K3];
__device__ __nv_bfloat16 g_Bo[(size_t)DMODEL * K3];

// ---------------------------------------------------------------------------
// Helpers
// ---------------------------------------------------------------------------
__device__ __forceinline__ uint32_t smem_u32(const void* p) {
    uint32_t a;
    asm("{ .reg .u64 t; cvta.to.shared.u64 t, %1; cvt.u32.u64 %0, t; }"
        : "=r"(a) : "l"(p));
    return a;
}
// 64B-row swizzle: XOR 16B-column (bits 4:5) with (row>>1)&3 (bits 7:8).
// Spreads the 8 rows of an ldmatrix access across distinct bank quadrants.
__device__ __forceinline__ uint32_t swz(uint32_t b) {
    return b ^ (((b >> 7) & 3u) << 4);
}

#define LDSM4(r0, r1, r2, r3, addr) \
    asm volatile("ldmatrix.sync.aligned.m8n8.x4.shared.b16 {%0,%1,%2,%3}, [%4];" \
                 : "=r"(r0), "=r"(r1), "=r"(r2), "=r"(r3) : "r"(addr))

__device__ __forceinline__ void mma16816(float* c, const uint32_t* a,
                                         uint32_t b0, uint32_t b1) {
    asm volatile(
        "mma.sync.aligned.m16n8k16.row.col.f32.bf16.bf16.f32 "
        "{%0,%1,%2,%3}, {%4,%5,%6,%7}, {%8,%9}, {%0,%1,%2,%3};"
        : "+f"(c[0]), "+f"(c[1]), "+f"(c[2]), "+f"(c[3])
        : "r"(a[0]), "r"(a[1]), "r"(a[2]), "r"(a[3]), "r"(b0), "r"(b1));
}

// ---------------------------------------------------------------------------
// Split conversions
// ---------------------------------------------------------------------------
// X[rows][DMODEL] fp32 -> A3[rows][K3] bf16 : cols [0,D)=hi, [D,2D)=lo, [2D,3D)=hi
__global__ void convA_kernel(const float* __restrict__ X,
                             __nv_bfloat16* __restrict__ A3, int total)
{
    int idx = (blockIdx.x * blockDim.x + threadIdx.x) * 4;
    if (idx >= total) return;
    float4 v = *(const float4*)(X + idx);
    int row = idx / DMODEL, col = idx % DMODEL;
    size_t b = (size_t)row * K3 + col;
    union { __nv_bfloat16 h[4]; uint2 u; } H, L;
    float x[4] = {v.x, v.y, v.z, v.w};
#pragma unroll
    for (int i = 0; i < 4; ++i) {
        H.h[i] = __float2bfloat16_rn(x[i]);
        L.h[i] = __float2bfloat16_rn(x[i] - __bfloat162float(H.h[i]));
    }
    *(uint2*)(A3 + b)              = H.u;
    *(uint2*)(A3 + b + DMODEL)     = L.u;
    *(uint2*)(A3 + b + 2 * DMODEL) = H.u;
}

// W[K=1536][N] fp32 -> Bt[N][K3] bf16 (transposed): cols [0,D)=hi, [D,2D)=hi, [2D,3D)=lo
__global__ void convW_kernel(const float* __restrict__ W,
                             __nv_bfloat16* __restrict__ Bt, int Ndim)
{
    __shared__ float tile[32][33];
    int n0 = blockIdx.x * 32, k0 = blockIdx.y * 32;
    int tx = threadIdx.x, ty = threadIdx.y;   // 32 x 8
#pragma unroll
    for (int q = 0; q < 4; ++q) {
        int k = k0 + ty + q * 8;
        tile[ty + q * 8][tx] = W[(size_t)k * Ndim + n0 + tx];
    }
    __syncthreads();
#pragma unroll
    for (int q = 0; q < 4; ++q) {
        int n = n0 + ty + q * 8;
        float v = tile[tx][ty + q * 8];
        __nv_bfloat16 hi = __float2bfloat16_rn(v);
        __nv_bfloat16 lo = __float2bfloat16_rn(v - __bfloat162float(hi));
        size_t b = (size_t)n * K3 + k0 + tx;
        Bt[b]              = hi;
        Bt[b + DMODEL]     = hi;
        Bt[b + 2 * DMODEL] = lo;
    }
}

// ---------------------------------------------------------------------------
// HMMA GEMM via mma.sync (bf16 in, fp32 accum):
//   C[m][n] = sum_k A3[m][k] * B3[n][k]
// CTA tile 128x128, BK=32, 256 threads = 8 warps (2x4), warp tile 64x32.
// Double-buffered swizzled smem, gmem prefetch into registers.
// EPI: += bias[n] + residual[m*N+n]
// ---------------------------------------------------------------------------
#define BK 32
#define NCHUNK (K3 / BK)   // 144

template<bool EPI>
__global__ __launch_bounds__(256)
void hmma_gemm(const __nv_bfloat16* __restrict__ A3,
               const __nv_bfloat16* __restrict__ B3,
               float* __restrict__ C, int Ntot,
               const float* __restrict__ bias, const float* __restrict__ residual)
{
    __shared__ __nv_bfloat16 smA[2][128 * BK];
    __shared__ __nv_bfloat16 smB[2][128 * BK];

    const int t   = threadIdx.x;
    const int wid = t >> 5;
    const int l   = t & 31;
    const int wm  = wid & 1;          // 0..1
    const int wn  = wid >> 1;         // 0..3
    const int m0  = blockIdx.y * 128;
    const int n0  = blockIdx.x * 128;

    const uint32_t aBase[2] = { smem_u32(smA[0]), smem_u32(smA[1]) };
    const uint32_t bBase[2] = { smem_u32(smB[0]), smem_u32(smB[1]) };

    float acc[4][4][4];
#pragma unroll
    for (int mi = 0; mi < 4; ++mi)
#pragma unroll
        for (int ni = 0; ni < 4; ++ni)
#pragma unroll
            for (int r = 0; r < 4; ++r) acc[mi][ni][r] = 0.f;

    // per-lane ldmatrix row/col components
    const int arow   = wm * 64 + (l & 15);                       // A row in tile
    const int ac16   = (l >> 4);                                 // +0/+1 16B col
    const int brow   = wn * 32 + (l & 7) + ((l >> 4) << 3);      // B row in tile
    const int bc16   = (l >> 3) & 1;

    // gmem prefetch registers (2 slots each: 512 x 16B per tile)
    uint4 ra[2], rb[2];
    const int srow[2] = { t >> 2, (t + 256) >> 2 };
    const int sc16[2] = { t & 3, t & 3 };

#define GLOAD(c)                                                                 \
    {                                                                            \
        int kc = (c) * BK;                                                       \
        _Pragma("unroll")                                                        \
        for (int i = 0; i < 2; ++i) {                                            \
            ra[i] = *(const uint4*)(A3 + (size_t)(m0 + srow[i]) * K3 + kc + sc16[i] * 8); \
            rb[i] = *(const uint4*)(B3 + (size_t)(n0 + srow[i]) * K3 + kc + sc16[i] * 8); \
        }                                                                        \
    }
#define SSTORE(buf)                                                              \
    {                                                                            \
        _Pragma("unroll")                                                        \
        for (int i = 0; i < 2; ++i) {                                            \
            uint32_t off = swz((uint32_t)(srow[i] * 64 + sc16[i] * 16));         \
            *(uint4*)((char*)smA[buf] + off) = ra[i];                            \
            *(uint4*)((char*)smB[buf] + off) = rb[i];                            \
        }                                                                        \
    }

    GLOAD(0);
    SSTORE(0);
    __syncthreads();

    for (int c = 0; c < NCHUNK; ++c) {
        const int buf = c & 1;
        if (c + 1 < NCHUNK) GLOAD(c + 1);

#pragma unroll
        for (int ks = 0; ks < 2; ++ks) {
            uint32_t afr[4][4];
#pragma unroll
            for (int mi = 0; mi < 4; ++mi) {
                uint32_t ad = aBase[buf] +
                    swz((uint32_t)((arow + mi * 16) * 64 + (ks * 2 + ac16) * 16));
                LDSM4(afr[mi][0], afr[mi][1], afr[mi][2], afr[mi][3], ad);
            }
            uint32_t bfr[2][4];
#pragma unroll
            for (int nb = 0; nb < 2; ++nb) {
                uint32_t bd = bBase[buf] +
                    swz((uint32_t)((brow + nb * 16) * 64 + (ks * 2 + bc16) * 16));
                LDSM4(bfr[nb][0], bfr[nb][1], bfr[nb][2], bfr[nb][3], bd);
            }
#pragma unroll
            for (int mi = 0; mi < 4; ++mi)
#pragma unroll
                for (int ni = 0; ni < 4; ++ni)
                    mma16816(acc[mi][ni], afr[mi],
                             bfr[ni >> 1][(ni & 1) * 2],
                             bfr[ni >> 1][(ni & 1) * 2 + 1]);
        }
        __syncthreads();
        if (c + 1 < NCHUNK) {
            SSTORE((c + 1) & 1);
            __syncthreads();
        }
    }

    // Epilogue: lane holds C[g][2t], C[g][2t+1], C[g+8][2t], C[g+8][2t+1]
    const int mrow = m0 + wm * 64 + (l >> 2);
    const int ncol = n0 + wn * 32 + 2 * (l & 3);
#pragma unroll
    for (int mi = 0; mi < 4; ++mi) {
#pragma unroll
        for (int ni = 0; ni < 4; ++ni) {
            int r  = mrow + mi * 16;
            int cc = ncol + ni * 8;
            size_t o0 = (size_t)r * Ntot + cc;
            size_t o1 = (size_t)(r + 8) * Ntot + cc;
            float2 v0 = make_float2(acc[mi][ni][0], acc[mi][ni][1]);
            float2 v1 = make_float2(acc[mi][ni][2], acc[mi][ni][3]);
            if (EPI) {
                float bx = bias[cc], by = bias[cc + 1];
                float2 r0 = *(const float2*)(residual + o0);
                float2 r1 = *(const float2*)(residual + o1);
                v0.x += bx + r0.x; v0.y += by + r0.y;
                v1.x += bx + r1.x; v1.y += by + r1.y;
            }
            *(float2*)(C + o0) = v0;
            *(float2*)(C + o1) = v1;
        }
    }
#undef GLOAD
#undef SSTORE
}

// ---------------------------------------------------------------------------
// Partial RoPE (unchanged)
// ---------------------------------------------------------------------------
__global__ void rope_kernel(float* __restrict__ X,
                            const float* __restrict__ cosb,
                            const float* __restrict__ sinb,
                            int nheads, int total)
{
    int idx = blockIdx.x * blockDim.x + threadIdx.x;
    if (idx >= total) return;
    int d   = idx & 15;
    int tmp = idx >> 4;
    int h   = tmp % nheads;
    int row = tmp / nheads;
    int s   = row & (SEQ - 1);

    float c  = cosb[s * ROT + d];
    float sn = sinb[s * ROT + d];
    float* p = X + (size_t)row * (nheads * HDIM) + h * HDIM;
    float xr = p[d];
    float xi = p[d + 16];
    p[d]      = xr * c - xi * sn;
    p[d + 16] = xi * c + xr * sn;
}

// ---------------------------------------------------------------------------
// Flash-style attention (unchanged from best passing kernel)
// ---------------------------------------------------------------------------
typedef unsigned long long u64;
__device__ __forceinline__ u64 ffma2(u64 a, u64 b, u64 c) {
    u64 d; asm("fma.rn.f32x2 %0, %1, %2, %3;" : "=l"(d) : "l"(a), "l"(b), "l"(c)); return d;
}
__device__ __forceinline__ u64 fmul2(u64 a, u64 b) {
    u64 d; asm("mul.rn.f32x2 %0, %1, %2;" : "=l"(d) : "l"(a), "l"(b)); return d;
}
__device__ __forceinline__ u64 pack2(float lo, float hi) {
    u64 d; asm("mov.b64 %0, {%1, %2};" : "=l"(d) : "f"(lo), "f"(hi)); return d;
}
__device__ __forceinline__ float2 unpack2(u64 v) {
    float lo, hi; asm("mov.b64 {%0, %1}, %2;" : "=f"(lo), "=f"(hi) : "l"(v));
    return make_float2(lo, hi);
}

__global__ __launch_bounds__(128)
void attn_kernel(const float* __restrict__ Q, const float* __restrict__ K,
                 const float* __restrict__ V, float* __restrict__ O)
{
    extern __shared__ float sm[];
    float* Ks = sm;            // 64*64
    float* Vs = sm + 4096;     // 64*64
    float* Ss = sm + 8192;     // 128*65

    const int tid = threadIdx.x;
    const int bh  = blockIdx.y;
    const int b   = bh / NHEADS;
    const int h   = bh % NHEADS;
    const int kvh = h / (NHEADS / KVHEADS);

    const int qrow = b * SEQ + blockIdx.x * 128 + tid;
    const float* qp = Q + (size_t)qrow * DMODEL + h * HDIM;

    u64 q2[32];
    {
        const ulonglong2* qp2 = (const ulonglong2*)qp;
#pragma unroll
        for (int i = 0; i < 16; ++i) {
            ulonglong2 v = qp2[i];
            q2[2 * i] = v.x; q2[2 * i + 1] = v.y;
        }
    }

    u64 acc2[32];
#pragma unroll
    for (int p = 0; p < 32; ++p) acc2[p] = 0ull;
    float m = -1e30f;
    float l = 0.f;

    const size_t kvbase = (size_t)b * SEQ * KVDIM + kvh * HDIM;

    for (int j0 = 0; j0 < SEQ; j0 += 64) {
        for (int i = tid; i < 64 * 16; i += 128) {
            int r  = i >> 4;
            int c4 = (i & 15) << 2;
            size_t goff = kvbase + (size_t)(j0 + r) * KVDIM + c4;
            *(float4*)&Ks[r * 64 + c4] = *(const float4*)(K + goff);
            *(float4*)&Vs[r * 64 + c4] = *(const float4*)(V + goff);
        }
        __syncthreads();

        float cmax = -1e30f;
        float* srow = Ss + tid * 65;
        for (int j = 0; j < 64; ++j) {
            const ulonglong2* kr = (const ulonglong2*)(Ks + j * 64);
            u64 s0 = 0ull, s1 = 0ull;
#pragma unroll
            for (int d8 = 0; d8 < 16; ++d8) {
                ulonglong2 kv = kr[d8];
                s0 = ffma2(q2[2 * d8],     kv.x, s0);
                s1 = ffma2(q2[2 * d8 + 1], kv.y, s1);
            }
            float2 f0 = unpack2(s0);
            float2 f1 = unpack2(s1);
            float s = ((f0.x + f1.x) + (f0.y + f1.y)) * 0.125f;
            cmax = fmaxf(cmax, s);
            srow[j] = s;
        }

        float mnew = fmaxf(m, cmax);
        float corr = __expf(m - mnew);
        l *= corr;
        u64 corr2 = pack2(corr, corr);
#pragma unroll
        for (int p = 0; p < 32; ++p) acc2[p] = fmul2(acc2[p], corr2);

        for (int j = 0; j < 64; ++j) {
            float p = __expf(srow[j] - mnew);
            l += p;
            u64 p2 = pack2(p, p);
            const ulonglong2* vr = (const ulonglong2*)(Vs + j * 64);
#pragma unroll
            for (int d8 = 0; d8 < 16; ++d8) {
                ulonglong2 vv = vr[d8];
                acc2[2 * d8]     = ffma2(p2, vv.x, acc2[2 * d8]);
                acc2[2 * d8 + 1] = ffma2(p2, vv.y, acc2[2 * d8 + 1]);
            }
        }
        m = mnew;
        __syncthreads();
    }

    float inv_l = 1.f / l;
    u64 il2 = pack2(inv_l, inv_l);
    float* op = O + (size_t)qrow * DMODEL + h * HDIM;
#pragma unroll
    for (int d8 = 0; d8 < 16; ++d8) {
        float2 a = unpack2(fmul2(acc2[2 * d8],     il2));
        float2 c = unpack2(fmul2(acc2[2 * d8 + 1], il2));
        float4 v = make_float4(a.x, a.y, c.x, c.y);
        *(float4*)(op + d8 * 4) = v;
    }
}

// ---------------------------------------------------------------------------
extern "C" void kernel_launch(void* const* d_in, const int* in_sizes, int n_in,
                              void* d_out, int out_size)
{
    const float* hidden = (const float*)d_in[0];
    const float* cosb   = (const float*)d_in[1];
    const float* sinb   = (const float*)d_in[2];
    const float* Wq     = (const float*)d_in[3];
    const float* Wk     = (const float*)d_in[4];
    const float* Wv     = (const float*)d_in[5];
    const float* Wo     = (const float*)d_in[6];
    const float* bo     = (const float*)d_in[7];
    float* out          = (float*)d_out;

    float *Qp, *Kp, *Vp, *Ap;
    __nv_bfloat16 *A3, *Bq, *Bk, *Bv, *Bo;
    cudaGetSymbolAddress((void**)&Qp, g_Q);
    cudaGetSymbolAddress((void**)&Kp, g_K);
    cudaGetSymbolAddress((void**)&Vp, g_V);
    cudaGetSymbolAddress((void**)&Ap, g_A);
    cudaGetSymbolAddress((void**)&A3, g_A3);
    cudaGetSymbolAddress((void**)&Bq, g_Bq);
    cudaGetSymbolAddress((void**)&Bk, g_Bk);
    cudaGetSymbolAddress((void**)&Bv, g_Bv);
    cudaGetSymbolAddress((void**)&Bo, g_Bo);

    // Split conversions
    {
        int tot = ROWS * DMODEL;
        convA_kernel<<<(tot / 4 + 255) / 256, 256>>>(hidden, A3, tot);
        convW_kernel<<<dim3(DMODEL / 32, DMODEL / 32), dim3(32, 8)>>>(Wq, Bq, DMODEL);
        convW_kernel<<<dim3(KVDIM  / 32, DMODEL / 32), dim3(32, 8)>>>(Wk, Bk, KVDIM);
        convW_kernel<<<dim3(KVDIM  / 32, DMODEL / 32), dim3(32, 8)>>>(Wv, Bv, KVDIM);
        convW_kernel<<<dim3(DMODEL / 32, DMODEL / 32), dim3(32, 8)>>>(Wo, Bo, DMODEL);
    }

    // QKV projections (HMMA tensor cores)
    hmma_gemm<false><<<dim3(DMODEL / 128, ROWS / 128), 256>>>(
        A3, Bq, Qp, DMODEL, nullptr, nullptr);
    hmma_gemm<false><<<dim3(KVDIM / 128, ROWS / 128), 256>>>(
        A3, Bk, Kp, KVDIM, nullptr, nullptr);
    hmma_gemm<false><<<dim3(KVDIM / 128, ROWS / 128), 256>>>(
        A3, Bv, Vp, KVDIM, nullptr, nullptr);

    // RoPE
    {
        int totq = ROWS * NHEADS * 16;
        rope_kernel<<<(totq + 255) / 256, 256>>>(Qp, cosb, sinb, NHEADS, totq);
        int totk = ROWS * KVHEADS * 16;
        rope_kernel<<<(totk + 255) / 256, 256>>>(Kp, cosb, sinb, KVHEADS, totk);
    }

    // Attention (scalar, unchanged)
    {
        const int smem = (4096 + 4096 + 128 * 65) * sizeof(float);
        cudaFuncSetAttribute(attn_kernel,
                             cudaFuncAttributeMaxDynamicSharedMemorySize, smem);
        attn_kernel<<<dim3(SEQ / 128, B_SZ * NHEADS), 128, smem>>>(Qp, Kp, Vp, Ap);
    }

    // Output projection: split attn output, then HMMA GEMM + bias + residual
    {
        int tot = ROWS * DMODEL;
        convA_kernel<<<(tot / 4 + 255) / 256, 256>>>(Ap, A3, tot);
        hmma_gemm<true><<<dim3(DMODEL / 128, ROWS / 128), 256>>>(
            A3, Bo, out, DMODEL, bo, hidden);
    }
}

// round 11
// speedup vs baseline: 2.7090x; 1.9753x over previous
#include <cuda_runtime.h>
#include <cuda_bf16.h>
#include <cstdint>
#include <math.h>

// Problem constants
#define B_SZ 2
#define SEQ 2048
#define DMODEL 1536
#define NHEADS 24
#define KVHEADS 6
#define HDIM 64
#define ROT 32
#define ROWS (B_SZ * SEQ)          // 4096
#define KVDIM (KVHEADS * HDIM)     // 384
#define K3 (3 * DMODEL)            // 4608  (split-K: [hi | lo | hi])

// Scratch (device globals; no allocation allowed)
__device__ float g_Q[ROWS * DMODEL];
__device__ float g_K[ROWS * KVDIM];
__device__ float g_V[ROWS * KVDIM];
__device__ float g_A[ROWS * DMODEL];
__device__ __nv_bfloat16 g_A3[(size_t)ROWS * K3];     // split activations
__device__ __nv_bfloat16 g_Bq[(size_t)DMODEL * K3];   // split+transposed weights
__device__ __nv_bfloat16 g_Bk[(size_t)KVDIM * K3];
__device__ __nv_bfloat16 g_Bv[(size_t)KVDIM * K3];
__device__ __nv_bfloat16 g_Bo[(size_t)DMODEL * K3];

// ---------------------------------------------------------------------------
// Helpers
// ---------------------------------------------------------------------------
__device__ __forceinline__ uint32_t smem_u32(const void* p) {
    uint32_t a;
    asm("{ .reg .u64 t; cvta.to.shared.u64 t, %1; cvt.u32.u64 %0, t; }"
        : "=r"(a) : "l"(p));
    return a;
}
// 64B-row swizzle (GEMM tiles, BK=32 bf16 rows)
__device__ __forceinline__ uint32_t swz(uint32_t b) {
    return b ^ (((b >> 7) & 3u) << 4);
}
// 128B-row swizzle (attention tiles, 64 bf16 per row)
__device__ __forceinline__ uint32_t swz128(uint32_t b) {
    return b ^ (((b >> 7) & 7u) << 4);
}

#define LDSM4(r0, r1, r2, r3, addr) \
    asm volatile("ldmatrix.sync.aligned.m8n8.x4.shared.b16 {%0,%1,%2,%3}, [%4];" \
                 : "=r"(r0), "=r"(r1), "=r"(r2), "=r"(r3) : "r"(addr))
#define LDSM4T(r0, r1, r2, r3, addr) \
    asm volatile("ldmatrix.sync.aligned.m8n8.x4.trans.shared.b16 {%0,%1,%2,%3}, [%4];" \
                 : "=r"(r0), "=r"(r1), "=r"(r2), "=r"(r3) : "r"(addr))

__device__ __forceinline__ void mma16816(float* c, const uint32_t* a,
                                         uint32_t b0, uint32_t b1) {
    asm volatile(
        "mma.sync.aligned.m16n8k16.row.col.f32.bf16.bf16.f32 "
        "{%0,%1,%2,%3}, {%4,%5,%6,%7}, {%8,%9}, {%0,%1,%2,%3};"
        : "+f"(c[0]), "+f"(c[1]), "+f"(c[2]), "+f"(c[3])
        : "r"(a[0]), "r"(a[1]), "r"(a[2]), "r"(a[3]), "r"(b0), "r"(b1));
}

__device__ __forceinline__ uint32_t packbf2(float lo, float hi) {
    __nv_bfloat162 h = __floats2bfloat162_rn(lo, hi);   // x=lo (low 16b), y=hi
    return *(uint32_t*)&h;
}

// ---------------------------------------------------------------------------
// Split conversions
// ---------------------------------------------------------------------------
__global__ void convA_kernel(const float* __restrict__ X,
                             __nv_bfloat16* __restrict__ A3, int total)
{
    int idx = (blockIdx.x * blockDim.x + threadIdx.x) * 4;
    if (idx >= total) return;
    float4 v = *(const float4*)(X + idx);
    int row = idx / DMODEL, col = idx % DMODEL;
    size_t b = (size_t)row * K3 + col;
    union { __nv_bfloat16 h[4]; uint2 u; } H, L;
    float x[4] = {v.x, v.y, v.z, v.w};
#pragma unroll
    for (int i = 0; i < 4; ++i) {
        H.h[i] = __float2bfloat16_rn(x[i]);
        L.h[i] = __float2bfloat16_rn(x[i] - __bfloat162float(H.h[i]));
    }
    *(uint2*)(A3 + b)              = H.u;
    *(uint2*)(A3 + b + DMODEL)     = L.u;
    *(uint2*)(A3 + b + 2 * DMODEL) = H.u;
}

__global__ void convW_kernel(const float* __restrict__ W,
                             __nv_bfloat16* __restrict__ Bt, int Ndim)
{
    __shared__ float tile[32][33];
    int n0 = blockIdx.x * 32, k0 = blockIdx.y * 32;
    int tx = threadIdx.x, ty = threadIdx.y;   // 32 x 8
#pragma unroll
    for (int q = 0; q < 4; ++q) {
        int k = k0 + ty + q * 8;
        tile[ty + q * 8][tx] = W[(size_t)k * Ndim + n0 + tx];
    }
    __syncthreads();
#pragma unroll
    for (int q = 0; q < 4; ++q) {
        int n = n0 + ty + q * 8;
        float v = tile[tx][ty + q * 8];
        __nv_bfloat16 hi = __float2bfloat16_rn(v);
        __nv_bfloat16 lo = __float2bfloat16_rn(v - __bfloat162float(hi));
        size_t b = (size_t)n * K3 + k0 + tx;
        Bt[b]              = hi;
        Bt[b + DMODEL]     = hi;
        Bt[b + 2 * DMODEL] = lo;
    }
}

// ---------------------------------------------------------------------------
// HMMA GEMM (unchanged from R8 passing kernel)
// ---------------------------------------------------------------------------
#define BK 32
#define NCHUNK (K3 / BK)   // 144

template<bool EPI>
__global__ __launch_bounds__(256)
void hmma_gemm(const __nv_bfloat16* __restrict__ A3,
               const __nv_bfloat16* __restrict__ B3,
               float* __restrict__ C, int Ntot,
               const float* __restrict__ bias, const float* __restrict__ residual)
{
    __shared__ __nv_bfloat16 smA[2][128 * BK];
    __shared__ __nv_bfloat16 smB[2][128 * BK];

    const int t   = threadIdx.x;
    const int wid = t >> 5;
    const int l   = t & 31;
    const int wm  = wid & 1;
    const int wn  = wid >> 1;
    const int m0  = blockIdx.y * 128;
    const int n0  = blockIdx.x * 128;

    const uint32_t aBase[2] = { smem_u32(smA[0]), smem_u32(smA[1]) };
    const uint32_t bBase[2] = { smem_u32(smB[0]), smem_u32(smB[1]) };

    float acc[4][4][4];
#pragma unroll
    for (int mi = 0; mi < 4; ++mi)
#pragma unroll
        for (int ni = 0; ni < 4; ++ni)
#pragma unroll
            for (int r = 0; r < 4; ++r) acc[mi][ni][r] = 0.f;

    const int arow   = wm * 64 + (l & 15);
    const int ac16   = (l >> 4);
    const int brow   = wn * 32 + (l & 7) + ((l >> 4) << 3);
    const int bc16   = (l >> 3) & 1;

    uint4 ra[2], rb[2];
    const int srow[2] = { t >> 2, (t + 256) >> 2 };
    const int sc16[2] = { t & 3, t & 3 };

#define GLOAD(c)                                                                 \
    {                                                                            \
        int kc = (c) * BK;                                                       \
        _Pragma("unroll")                                                        \
        for (int i = 0; i < 2; ++i) {                                            \
            ra[i] = *(const uint4*)(A3 + (size_t)(m0 + srow[i]) * K3 + kc + sc16[i] * 8); \
            rb[i] = *(const uint4*)(B3 + (size_t)(n0 + srow[i]) * K3 + kc + sc16[i] * 8); \
        }                                                                        \
    }
#define SSTORE(buf)                                                              \
    {                                                                            \
        _Pragma("unroll")                                                        \
        for (int i = 0; i < 2; ++i) {                                            \
            uint32_t off = swz((uint32_t)(srow[i] * 64 + sc16[i] * 16));         \
            *(uint4*)((char*)smA[buf] + off) = ra[i];                            \
            *(uint4*)((char*)smB[buf] + off) = rb[i];                            \
        }                                                                        \
    }

    GLOAD(0);
    SSTORE(0);
    __syncthreads();

    for (int c = 0; c < NCHUNK; ++c) {
        const int buf = c & 1;
        if (c + 1 < NCHUNK) GLOAD(c + 1);

#pragma unroll
        for (int ks = 0; ks < 2; ++ks) {
            uint32_t afr[4][4];
#pragma unroll
            for (int mi = 0; mi < 4; ++mi) {
                uint32_t ad = aBase[buf] +
                    swz((uint32_t)((arow + mi * 16) * 64 + (ks * 2 + ac16) * 16));
                LDSM4(afr[mi][0], afr[mi][1], afr[mi][2], afr[mi][3], ad);
            }
            uint32_t bfr[2][4];
#pragma unroll
            for (int nb = 0; nb < 2; ++nb) {
                uint32_t bd = bBase[buf] +
                    swz((uint32_t)((brow + nb * 16) * 64 + (ks * 2 + bc16) * 16));
                LDSM4(bfr[nb][0], bfr[nb][1], bfr[nb][2], bfr[nb][3], bd);
            }
#pragma unroll
            for (int mi = 0; mi < 4; ++mi)
#pragma unroll
                for (int ni = 0; ni < 4; ++ni)
                    mma16816(acc[mi][ni], afr[mi],
                             bfr[ni >> 1][(ni & 1) * 2],
                             bfr[ni >> 1][(ni & 1) * 2 + 1]);
        }
        __syncthreads();
        if (c + 1 < NCHUNK) {
            SSTORE((c + 1) & 1);
            __syncthreads();
        }
    }

    const int mrow = m0 + wm * 64 + (l >> 2);
    const int ncol = n0 + wn * 32 + 2 * (l & 3);
#pragma unroll
    for (int mi = 0; mi < 4; ++mi) {
#pragma unroll
        for (int ni = 0; ni < 4; ++ni) {
            int r  = mrow + mi * 16;
            int cc = ncol + ni * 8;
            size_t o0 = (size_t)r * Ntot + cc;
            size_t o1 = (size_t)(r + 8) * Ntot + cc;
            float2 v0 = make_float2(acc[mi][ni][0], acc[mi][ni][1]);
            float2 v1 = make_float2(acc[mi][ni][2], acc[mi][ni][3]);
            if (EPI) {
                float bx = bias[cc], by = bias[cc + 1];
                float2 r0 = *(const float2*)(residual + o0);
                float2 r1 = *(const float2*)(residual + o1);
                v0.x += bx + r0.x; v0.y += by + r0.y;
                v1.x += bx + r1.x; v1.y += by + r1.y;
            }
            *(float2*)(C + o0) = v0;
            *(float2*)(C + o1) = v1;
        }
    }
#undef GLOAD
#undef SSTORE
}

// ---------------------------------------------------------------------------
// Partial RoPE (unchanged)
// ---------------------------------------------------------------------------
__global__ void rope_kernel(float* __restrict__ X,
                            const float* __restrict__ cosb,
                            const float* __restrict__ sinb,
                            int nheads, int total)
{
    int idx = blockIdx.x * blockDim.x + threadIdx.x;
    if (idx >= total) return;
    int d   = idx & 15;
    int tmp = idx >> 4;
    int h   = tmp % nheads;
    int row = tmp / nheads;
    int s   = row & (SEQ - 1);

    float c  = cosb[s * ROT + d];
    float sn = sinb[s * ROT + d];
    float* p = X + (size_t)row * (nheads * HDIM) + h * HDIM;
    float xr = p[d];
    float xi = p[d + 16];
    p[d]      = xr * c - xi * sn;
    p[d + 16] = xi * c + xr * sn;
}

// ---------------------------------------------------------------------------
// Tensor-core flash attention with 3-term bf16 split on both matmuls.
// grid = (SEQ/128, B*NHEADS), 256 threads = 8 warps x 16 q-rows.
// smem: khi/klo/vhi/vlo, each 128x64 bf16 (16KB) = 64KB (Q staged in khi/klo).
// ---------------------------------------------------------------------------
#define ATTN_SMEM 65536

__global__ __launch_bounds__(256)
void attn_mma(const float* __restrict__ Q, const float* __restrict__ K,
              const float* __restrict__ V, float* __restrict__ O)
{
    extern __shared__ char sm[];
    char* sKhi = sm;
    char* sKlo = sm + 16384;
    char* sVhi = sm + 32768;
    char* sVlo = sm + 49152;
    const uint32_t bKhi = smem_u32(sKhi);
    const uint32_t bKlo = smem_u32(sKlo);
    const uint32_t bVhi = smem_u32(sVhi);
    const uint32_t bVlo = smem_u32(sVlo);

    const int t   = threadIdx.x;
    const int wid = t >> 5;
    const int l   = t & 31;
    const int bh  = blockIdx.y;
    const int b   = bh / NHEADS;
    const int h   = bh % NHEADS;
    const int kvh = h >> 2;                 // NHEADS/KVHEADS = 4
    const int q0  = blockIdx.x * 128;

    // ---- stage Q (scaled by 1/8, split hi/lo) into sKhi/sKlo ----
    {
        const float* Qb = Q + ((size_t)(b * SEQ + q0)) * DMODEL + h * HDIM;
        for (int i = t; i < 128 * 16; i += 256) {
            int r  = i >> 4;
            int c4 = (i & 15) << 2;
            float4 v = *(const float4*)(Qb + (size_t)r * DMODEL + c4);
            float x[4] = {v.x * 0.125f, v.y * 0.125f, v.z * 0.125f, v.w * 0.125f};
            union { __nv_bfloat16 hh[4]; uint2 u; } H, L;
#pragma unroll
            for (int j = 0; j < 4; ++j) {
                H.hh[j] = __float2bfloat16_rn(x[j]);
                L.hh[j] = __float2bfloat16_rn(x[j] - __bfloat162float(H.hh[j]));
            }
            uint32_t off = swz128((uint32_t)(r * 128 + c4 * 2));
            *(uint2*)(sKhi + off) = H.u;
            *(uint2*)(sKlo + off) = L.u;
        }
    }
    __syncthreads();

    // ---- load Q fragments into registers (per warp: 16 rows, 4 k-steps) ----
    uint32_t qhiF[4][4], qloF[4][4];
    {
        const int arw = wid * 16 + (l & 7) + ((l >> 3) & 1) * 8;
        const int ac  = ((l >> 4) & 1) * 16;
#pragma unroll
        for (int ks = 0; ks < 4; ++ks) {
            uint32_t off = swz128((uint32_t)(arw * 128 + ks * 32 + ac));
            LDSM4(qhiF[ks][0], qhiF[ks][1], qhiF[ks][2], qhiF[ks][3], bKhi + off);
            LDSM4(qloF[ks][0], qloF[ks][1], qloF[ks][2], qloF[ks][3], bKlo + off);
        }
    }
    __syncthreads();

    float oacc[8][4];
#pragma unroll
    for (int nt = 0; nt < 8; ++nt)
#pragma unroll
        for (int r = 0; r < 4; ++r) oacc[nt][r] = 0.f;
    float m0 = -1e30f, m1 = -1e30f;
    float l0 = 0.f, l1 = 0.f;

    const size_t kvrow0 = (size_t)b * SEQ;

    for (int j0 = 0; j0 < SEQ; j0 += 128) {
        // ---- stage K,V chunk (split hi/lo) ----
        {
            const float* Kb = K + (kvrow0 + j0) * KVDIM + kvh * HDIM;
            const float* Vb = V + (kvrow0 + j0) * KVDIM + kvh * HDIM;
            for (int i = t; i < 128 * 16; i += 256) {
                int r  = i >> 4;
                int c4 = (i & 15) << 2;
                uint32_t off = swz128((uint32_t)(r * 128 + c4 * 2));
                float4 kv = *(const float4*)(Kb + (size_t)r * KVDIM + c4);
                {
                    float x[4] = {kv.x, kv.y, kv.z, kv.w};
                    union { __nv_bfloat16 hh[4]; uint2 u; } H, L;
#pragma unroll
                    for (int j = 0; j < 4; ++j) {
                        H.hh[j] = __float2bfloat16_rn(x[j]);
                        L.hh[j] = __float2bfloat16_rn(x[j] - __bfloat162float(H.hh[j]));
                    }
                    *(uint2*)(sKhi + off) = H.u;
                    *(uint2*)(sKlo + off) = L.u;
                }
                float4 vv = *(const float4*)(Vb + (size_t)r * KVDIM + c4);
                {
                    float x[4] = {vv.x, vv.y, vv.z, vv.w};
                    union { __nv_bfloat16 hh[4]; uint2 u; } H, L;
#pragma unroll
                    for (int j = 0; j < 4; ++j) {
                        H.hh[j] = __float2bfloat16_rn(x[j]);
                        L.hh[j] = __float2bfloat16_rn(x[j] - __bfloat162float(H.hh[j]));
                    }
                    *(uint2*)(sVhi + off) = H.u;
                    *(uint2*)(sVlo + off) = L.u;
                }
            }
        }
        __syncthreads();

        // ---- S = Q'K'^T (3-term split), 16 n-tiles of 8 kv cols ----
        float sacc[16][4];
#pragma unroll
        for (int nt = 0; nt < 16; ++nt)
#pragma unroll
            for (int r = 0; r < 4; ++r) sacc[nt][r] = 0.f;

        {
            const int brw = (l & 7) + ((l >> 4) & 1) * 8;   // + np*16
            const int bc  = ((l >> 3) & 1) * 16;            // + ks*32
#pragma unroll
            for (int ks = 0; ks < 4; ++ks) {
#pragma unroll
                for (int np = 0; np < 8; ++np) {
                    uint32_t off = swz128((uint32_t)((np * 16 + brw) * 128 + ks * 32 + bc));
                    uint32_t bh0, bh1, bh2, bh3, bl0, bl1, bl2, bl3;
                    LDSM4(bh0, bh1, bh2, bh3, bKhi + off);
                    LDSM4(bl0, bl1, bl2, bl3, bKlo + off);
                    mma16816(sacc[2 * np],     qhiF[ks], bh0, bh1);
                    mma16816(sacc[2 * np + 1], qhiF[ks], bh2, bh3);
                    mma16816(sacc[2 * np],     qloF[ks], bh0, bh1);
                    mma16816(sacc[2 * np + 1], qloF[ks], bh2, bh3);
                    mma16816(sacc[2 * np],     qhiF[ks], bl0, bl1);
                    mma16816(sacc[2 * np + 1], qhiF[ks], bl2, bl3);
                }
            }
        }

        // ---- online softmax ----
        float mx0 = -1e30f, mx1 = -1e30f;
#pragma unroll
        for (int nt = 0; nt < 16; ++nt) {
            mx0 = fmaxf(mx0, fmaxf(sacc[nt][0], sacc[nt][1]));
            mx1 = fmaxf(mx1, fmaxf(sacc[nt][2], sacc[nt][3]));
        }
        mx0 = fmaxf(mx0, __shfl_xor_sync(0xffffffff, mx0, 1));
        mx0 = fmaxf(mx0, __shfl_xor_sync(0xffffffff, mx0, 2));
        mx1 = fmaxf(mx1, __shfl_xor_sync(0xffffffff, mx1, 1));
        mx1 = fmaxf(mx1, __shfl_xor_sync(0xffffffff, mx1, 2));

        float mn0 = fmaxf(m0, mx0), mn1 = fmaxf(m1, mx1);
        float cr0 = __expf(m0 - mn0), cr1 = __expf(m1 - mn1);
        m0 = mn0; m1 = mn1;
        l0 *= cr0; l1 *= cr1;
#pragma unroll
        for (int nt = 0; nt < 8; ++nt) {
            oacc[nt][0] *= cr0; oacc[nt][1] *= cr0;
            oacc[nt][2] *= cr1; oacc[nt][3] *= cr1;
        }

        // exp in place
#pragma unroll
        for (int nt = 0; nt < 16; ++nt) {
            sacc[nt][0] = __expf(sacc[nt][0] - mn0);
            sacc[nt][1] = __expf(sacc[nt][1] - mn0);
            sacc[nt][2] = __expf(sacc[nt][2] - mn1);
            sacc[nt][3] = __expf(sacc[nt][3] - mn1);
            l0 += sacc[nt][0] + sacc[nt][1];
            l1 += sacc[nt][2] + sacc[nt][3];
        }

        // ---- O += P V (3-term split), per k-tile repack P ----
        {
            const int vrw = (l & 7) + ((l >> 3) & 1) * 8;   // + kt*16
            const int vc  = ((l >> 4) & 1) * 16;            // + vp*32
#pragma unroll
            for (int kt = 0; kt < 8; ++kt) {
                float* sa = sacc[2 * kt];
                float* sb = sacc[2 * kt + 1];
                uint32_t ahi[4], alo[4];
                ahi[0] = packbf2(sa[0], sa[1]);
                ahi[1] = packbf2(sa[2], sa[3]);
                ahi[2] = packbf2(sb[0], sb[1]);
                ahi[3] = packbf2(sb[2], sb[3]);
                {
                    __nv_bfloat162 h0 = *(__nv_bfloat162*)&ahi[0];
                    __nv_bfloat162 h1 = *(__nv_bfloat162*)&ahi[1];
                    __nv_bfloat162 h2 = *(__nv_bfloat162*)&ahi[2];
                    __nv_bfloat162 h3 = *(__nv_bfloat162*)&ahi[3];
                    alo[0] = packbf2(sa[0] - __bfloat162float(h0.x), sa[1] - __bfloat162float(h0.y));
                    alo[1] = packbf2(sa[2] - __bfloat162float(h1.x), sa[3] - __bfloat162float(h1.y));
                    alo[2] = packbf2(sb[0] - __bfloat162float(h2.x), sb[1] - __bfloat162float(h2.y));
                    alo[3] = packbf2(sb[2] - __bfloat162float(h3.x), sb[3] - __bfloat162float(h3.y));
                }
#pragma unroll
                for (int vp = 0; vp < 4; ++vp) {
                    uint32_t off = swz128((uint32_t)((kt * 16 + vrw) * 128 + vp * 32 + vc));
                    uint32_t vh0, vh1, vh2, vh3, vl0, vl1, vl2, vl3;
                    LDSM4T(vh0, vh1, vh2, vh3, bVhi + off);
                    LDSM4T(vl0, vl1, vl2, vl3, bVlo + off);
                    mma16816(oacc[2 * vp],     ahi, vh0, vh1);
                    mma16816(oacc[2 * vp + 1], ahi, vh2, vh3);
                    mma16816(oacc[2 * vp],     alo, vh0, vh1);
                    mma16816(oacc[2 * vp + 1], alo, vh2, vh3);
                    mma16816(oacc[2 * vp],     ahi, vl0, vl1);
                    mma16816(oacc[2 * vp + 1], ahi, vl2, vl3);
                }
            }
        }
        __syncthreads();
    }

    // ---- finalize: reduce row sums, scale, write ----
    l0 += __shfl_xor_sync(0xffffffff, l0, 1);
    l0 += __shfl_xor_sync(0xffffffff, l0, 2);
    l1 += __shfl_xor_sync(0xffffffff, l1, 1);
    l1 += __shfl_xor_sync(0xffffffff, l1, 2);
    float inv0 = 1.f / l0, inv1 = 1.f / l1;

    const int row0 = b * SEQ + q0 + wid * 16 + (l >> 2);
    const int colb = h * HDIM + 2 * (l & 3);
#pragma unroll
    for (int nt = 0; nt < 8; ++nt) {
        int cc = colb + nt * 8;
        *(float2*)(O + (size_t)row0 * DMODEL + cc) =
            make_float2(oacc[nt][0] * inv0, oacc[nt][1] * inv0);
        *(float2*)(O + (size_t)(row0 + 8) * DMODEL + cc) =
            make_float2(oacc[nt][2] * inv1, oacc[nt][3] * inv1);
    }
}

// ---------------------------------------------------------------------------
extern "C" void kernel_launch(void* const* d_in, const int* in_sizes, int n_in,
                              void* d_out, int out_size)
{
    const float* hidden = (const float*)d_in[0];
    const float* cosb   = (const float*)d_in[1];
    const float* sinb   = (const float*)d_in[2];
    const float* Wq     = (const float*)d_in[3];
    const float* Wk     = (const float*)d_in[4];
    const float* Wv     = (const float*)d_in[5];
    const float* Wo     = (const float*)d_in[6];
    const float* bo     = (const float*)d_in[7];
    float* out          = (float*)d_out;

    float *Qp, *Kp, *Vp, *Ap;
    __nv_bfloat16 *A3, *Bq, *Bk, *Bv, *Bo;
    cudaGetSymbolAddress((void**)&Qp, g_Q);
    cudaGetSymbolAddress((void**)&Kp, g_K);
    cudaGetSymbolAddress((void**)&Vp, g_V);
    cudaGetSymbolAddress((void**)&Ap, g_A);
    cudaGetSymbolAddress((void**)&A3, g_A3);
    cudaGetSymbolAddress((void**)&Bq, g_Bq);
    cudaGetSymbolAddress((void**)&Bk, g_Bk);
    cudaGetSymbolAddress((void**)&Bv, g_Bv);
    cudaGetSymbolAddress((void**)&Bo, g_Bo);

    // Split conversions
    {
        int tot = ROWS * DMODEL;
        convA_kernel<<<(tot / 4 + 255) / 256, 256>>>(hidden, A3, tot);
        convW_kernel<<<dim3(DMODEL / 32, DMODEL / 32), dim3(32, 8)>>>(Wq, Bq, DMODEL);
        convW_kernel<<<dim3(KVDIM  / 32, DMODEL / 32), dim3(32, 8)>>>(Wk, Bk, KVDIM);
        convW_kernel<<<dim3(KVDIM  / 32, DMODEL / 32), dim3(32, 8)>>>(Wv, Bv, KVDIM);
        convW_kernel<<<dim3(DMODEL / 32, DMODEL / 32), dim3(32, 8)>>>(Wo, Bo, DMODEL);
    }

    // QKV projections (HMMA tensor cores)
    hmma_gemm<false><<<dim3(DMODEL / 128, ROWS / 128), 256>>>(
        A3, Bq, Qp, DMODEL, nullptr, nullptr);
    hmma_gemm<false><<<dim3(KVDIM / 128, ROWS / 128), 256>>>(
        A3, Bk, Kp, KVDIM, nullptr, nullptr);
    hmma_gemm<false><<<dim3(KVDIM / 128, ROWS / 128), 256>>>(
        A3, Bv, Vp, KVDIM, nullptr, nullptr);

    // RoPE
    {
        int totq = ROWS * NHEADS * 16;
        rope_kernel<<<(totq + 255) / 256, 256>>>(Qp, cosb, sinb, NHEADS, totq);
        int totk = ROWS * KVHEADS * 16;
        rope_kernel<<<(totk + 255) / 256, 256>>>(Kp, cosb, sinb, KVHEADS, totk);
    }

    // Attention (tensor cores, split-precision)
    {
        cudaFuncSetAttribute(attn_mma,
                             cudaFuncAttributeMaxDynamicSharedMemorySize, ATTN_SMEM);
        attn_mma<<<dim3(SEQ / 128, B_SZ * NHEADS), 256, ATTN_SMEM>>>(Qp, Kp, Vp, Ap);
    }

    // Output projection: split attn output, then HMMA GEMM + bias + residual
    {
        int tot = ROWS * DMODEL;
        convA_kernel<<<(tot / 4 + 255) / 256, 256>>>(Ap, A3, tot);
        hmma_gemm<true><<<dim3(DMODEL / 128, ROWS / 128), 256>>>(
            A3, Bo, out, DMODEL, bo, hidden);
    }
}

// round 14
// speedup vs baseline: 3.2973x; 1.2171x over previous
#include <cuda_runtime.h>
#include <cuda_bf16.h>
#include <cstdint>
#include <math.h>

// Problem constants
#define B_SZ 2
#define SEQ 2048
#define DMODEL 1536
#define NHEADS 24
#define KVHEADS 6
#define HDIM 64
#define ROT 32
#define ROWS (B_SZ * SEQ)          // 4096
#define KVDIM (KVHEADS * HDIM)     // 384
#define K3 (3 * DMODEL)            // 4608  (split-K: [hi | lo | hi])
#define NQKV (DMODEL + 2 * KVDIM)  // 2304 fused QKV output width
#define KVROWS (B_SZ * KVHEADS * SEQ)

// Scratch (device globals; no allocation allowed)
__device__ float g_QKV[(size_t)ROWS * NQKV];
__device__ __nv_bfloat16 g_A3[(size_t)ROWS * K3];      // split activations
__device__ __nv_bfloat16 g_Bqkv[(size_t)NQKV * K3];    // fused split weights
__device__ __nv_bfloat16 g_Bo[(size_t)DMODEL * K3];
__device__ __nv_bfloat16 g_Khi[(size_t)KVROWS * HDIM]; // head-major, rope'd
__device__ __nv_bfloat16 g_Klo[(size_t)KVROWS * HDIM];
__device__ __nv_bfloat16 g_Vhi[(size_t)KVROWS * HDIM];
__device__ __nv_bfloat16 g_Vlo[(size_t)KVROWS * HDIM];

// ---------------------------------------------------------------------------
// Helpers
// ---------------------------------------------------------------------------
__device__ __forceinline__ uint32_t smem_u32(const void* p) {
    uint32_t a;
    asm("{ .reg .u64 t; cvta.to.shared.u64 t, %1; cvt.u32.u64 %0, t; }"
        : "=r"(a) : "l"(p));
    return a;
}
__device__ __forceinline__ uint32_t swz(uint32_t b) {        // 64B-row tiles
    return b ^ (((b >> 7) & 3u) << 4);
}
__device__ __forceinline__ uint32_t swz128(uint32_t b) {     // 128B-row tiles
    return b ^ (((b >> 7) & 7u) << 4);
}

#define LDSM4(r0, r1, r2, r3, addr) \
    asm volatile("ldmatrix.sync.aligned.m8n8.x4.shared.b16 {%0,%1,%2,%3}, [%4];" \
                 : "=r"(r0), "=r"(r1), "=r"(r2), "=r"(r3) : "r"(addr))
#define LDSM4T(r0, r1, r2, r3, addr) \
    asm volatile("ldmatrix.sync.aligned.m8n8.x4.trans.shared.b16 {%0,%1,%2,%3}, [%4];" \
                 : "=r"(r0), "=r"(r1), "=r"(r2), "=r"(r3) : "r"(addr))
#define CPASYNC16(sm, gm) \
    asm volatile("cp.async.ca.shared.global [%0], [%1], 16;" :: "r"(sm), "l"(gm))
#define CPASYNC_FENCE() \
    do { asm volatile("cp.async.commit_group;" ::: "memory"); \
         asm volatile("cp.async.wait_group 0;" ::: "memory"); } while (0)

__device__ __forceinline__ void mma16816(float* c, const uint32_t* a,
                                         uint32_t b0, uint32_t b1) {
    asm volatile(
        "mma.sync.aligned.m16n8k16.row.col.f32.bf16.bf16.f32 "
        "{%0,%1,%2,%3}, {%4,%5,%6,%7}, {%8,%9}, {%0,%1,%2,%3};"
        : "+f"(c[0]), "+f"(c[1]), "+f"(c[2]), "+f"(c[3])
        : "r"(a[0]), "r"(a[1]), "r"(a[2]), "r"(a[3]), "r"(b0), "r"(b1));
}

__device__ __forceinline__ uint32_t packbf2(float lo, float hi) {
    __nv_bfloat162 h = __floats2bfloat162_rn(lo, hi);
    return *(uint32_t*)&h;
}

// ---------------------------------------------------------------------------
// Split conversions
// ---------------------------------------------------------------------------
__global__ void convA_kernel(const float* __restrict__ X,
                             __nv_bfloat16* __restrict__ A3, int total)
{
    int idx = (blockIdx.x * blockDim.x + threadIdx.x) * 4;
    if (idx >= total) return;
    float4 v = *(const float4*)(X + idx);
    int row = idx / DMODEL, col = idx % DMODEL;
    size_t b = (size_t)row * K3 + col;
    union { __nv_bfloat16 h[4]; uint2 u; } H, L;
    float x[4] = {v.x, v.y, v.z, v.w};
#pragma unroll
    for (int i = 0; i < 4; ++i) {
        H.h[i] = __float2bfloat16_rn(x[i]);
        L.h[i] = __float2bfloat16_rn(x[i] - __bfloat162float(H.h[i]));
    }
    *(uint2*)(A3 + b)              = H.u;
    *(uint2*)(A3 + b + DMODEL)     = L.u;
    *(uint2*)(A3 + b + 2 * DMODEL) = H.u;
}

__global__ void convW_kernel(const float* __restrict__ W,
                             __nv_bfloat16* __restrict__ Bt, int Ndim)
{
    __shared__ float tile[32][33];
    int n0 = blockIdx.x * 32, k0 = blockIdx.y * 32;
    int tx = threadIdx.x, ty = threadIdx.y;   // 32 x 8
#pragma unroll
    for (int q = 0; q < 4; ++q) {
        int k = k0 + ty + q * 8;
        tile[ty + q * 8][tx] = W[(size_t)k * Ndim + n0 + tx];
    }
    __syncthreads();
#pragma unroll
    for (int q = 0; q < 4; ++q) {
        int n = n0 + ty + q * 8;
        float v = tile[tx][ty + q * 8];
        __nv_bfloat16 hi = __float2bfloat16_rn(v);
        __nv_bfloat16 lo = __float2bfloat16_rn(v - __bfloat162float(hi));
        size_t b = (size_t)n * K3 + k0 + tx;
        Bt[b]              = hi;
        Bt[b + DMODEL]     = hi;
        Bt[b + 2 * DMODEL] = lo;
    }
}

// ---------------------------------------------------------------------------
// HMMA GEMM
// ---------------------------------------------------------------------------
#define BK 32
#define NCHUNK (K3 / BK)   // 144

template<bool EPI>
__global__ __launch_bounds__(256)
void hmma_gemm(const __nv_bfloat16* __restrict__ A3,
               const __nv_bfloat16* __restrict__ B3,
               float* __restrict__ C, int Ntot,
               const float* __restrict__ bias, const float* __restrict__ residual)
{
    __shared__ __nv_bfloat16 smA[2][128 * BK];
    __shared__ __nv_bfloat16 smB[2][128 * BK];

    const int t   = threadIdx.x;
    const int wid = t >> 5;
    const int l   = t & 31;
    const int wm  = wid & 1;
    const int wn  = wid >> 1;
    const int m0  = blockIdx.y * 128;
    const int n0  = blockIdx.x * 128;

    const uint32_t aBase[2] = { smem_u32(smA[0]), smem_u32(smA[1]) };
    const uint32_t bBase[2] = { smem_u32(smB[0]), smem_u32(smB[1]) };

    float acc[4][4][4];
#pragma unroll
    for (int mi = 0; mi < 4; ++mi)
#pragma unroll
        for (int ni = 0; ni < 4; ++ni)
#pragma unroll
            for (int r = 0; r < 4; ++r) acc[mi][ni][r] = 0.f;

    const int arow   = wm * 64 + (l & 15);
    const int ac16   = (l >> 4);
    const int brow   = wn * 32 + (l & 7) + ((l >> 4) << 3);
    const int bc16   = (l >> 3) & 1;

    uint4 ra[2], rb[2];
    const int srow[2] = { t >> 2, (t + 256) >> 2 };
    const int sc16[2] = { t & 3, t & 3 };

#define GLOAD(c)                                                                 \
    {                                                                            \
        int kc = (c) * BK;                                                       \
        _Pragma("unroll")                                                        \
        for (int i = 0; i < 2; ++i) {                                            \
            ra[i] = *(const uint4*)(A3 + (size_t)(m0 + srow[i]) * K3 + kc + sc16[i] * 8); \
            rb[i] = *(const uint4*)(B3 + (size_t)(n0 + srow[i]) * K3 + kc + sc16[i] * 8); \
        }                                                                        \
    }
#define SSTORE(buf)                                                              \
    {                                                                            \
        _Pragma("unroll")                                                        \
        for (int i = 0; i < 2; ++i) {                                            \
            uint32_t off = swz((uint32_t)(srow[i] * 64 + sc16[i] * 16));         \
            *(uint4*)((char*)smA[buf] + off) = ra[i];                            \
            *(uint4*)((char*)smB[buf] + off) = rb[i];                            \
        }                                                                        \
    }

    GLOAD(0);
    SSTORE(0);
    __syncthreads();

    for (int c = 0; c < NCHUNK; ++c) {
        const int buf = c & 1;
        if (c + 1 < NCHUNK) GLOAD(c + 1);

#pragma unroll
        for (int ks = 0; ks < 2; ++ks) {
            uint32_t afr[4][4];
#pragma unroll
            for (int mi = 0; mi < 4; ++mi) {
                uint32_t ad = aBase[buf] +
                    swz((uint32_t)((arow + mi * 16) * 64 + (ks * 2 + ac16) * 16));
                LDSM4(afr[mi][0], afr[mi][1], afr[mi][2], afr[mi][3], ad);
            }
            uint32_t bfr[2][4];
#pragma unroll
            for (int nb = 0; nb < 2; ++nb) {
                uint32_t bd = bBase[buf] +
                    swz((uint32_t)((brow + nb * 16) * 64 + (ks * 2 + bc16) * 16));
                LDSM4(bfr[nb][0], bfr[nb][1], bfr[nb][2], bfr[nb][3], bd);
            }
#pragma unroll
            for (int mi = 0; mi < 4; ++mi)
#pragma unroll
                for (int ni = 0; ni < 4; ++ni)
                    mma16816(acc[mi][ni], afr[mi],
                             bfr[ni >> 1][(ni & 1) * 2],
                             bfr[ni >> 1][(ni & 1) * 2 + 1]);
        }
        __syncthreads();
        if (c + 1 < NCHUNK) {
            SSTORE((c + 1) & 1);
            __syncthreads();
        }
    }

    const int mrow = m0 + wm * 64 + (l >> 2);
    const int ncol = n0 + wn * 32 + 2 * (l & 3);
#pragma unroll
    for (int mi = 0; mi < 4; ++mi) {
#pragma unroll
        for (int ni = 0; ni < 4; ++ni) {
            int r  = mrow + mi * 16;
            int cc = ncol + ni * 8;
            size_t o0 = (size_t)r * Ntot + cc;
            size_t o1 = (size_t)(r + 8) * Ntot + cc;
            float2 v0 = make_float2(acc[mi][ni][0], acc[mi][ni][1]);
            float2 v1 = make_float2(acc[mi][ni][2], acc[mi][ni][3]);
            if (EPI) {
                float bx = bias[cc], by = bias[cc + 1];
                float2 r0 = *(const float2*)(residual + o0);
                float2 r1 = *(const float2*)(residual + o1);
                v0.x += bx + r0.x; v0.y += by + r0.y;
                v1.x += bx + r1.x; v1.y += by + r1.y;
            }
            *(float2*)(C + o0) = v0;
            *(float2*)(C + o1) = v1;
        }
    }
#undef GLOAD
#undef SSTORE
}

// ---------------------------------------------------------------------------
// Partial RoPE on Q inside fused QKV buffer (row stride NQKV)
// ---------------------------------------------------------------------------
__global__ void ropeQ_kernel(float* __restrict__ X,
                             const float* __restrict__ cosb,
                             const float* __restrict__ sinb, int total)
{
    int idx = blockIdx.x * blockDim.x + threadIdx.x;
    if (idx >= total) return;
    int d   = idx & 15;
    int tmp = idx >> 4;
    int h   = tmp % NHEADS;
    int row = tmp / NHEADS;
    int s   = row & (SEQ - 1);

    float c  = cosb[s * ROT + d];
    float sn = sinb[s * ROT + d];
    float* p = X + (size_t)row * NQKV + h * HDIM;
    float xr = p[d];
    float xi = p[d + 16];
    p[d]      = xr * c - xi * sn;
    p[d + 16] = xi * c + xr * sn;
}

// ---------------------------------------------------------------------------
// conv_kv: RoPE K + split K/V into head-major bf16 hi/lo buffers.
// ---------------------------------------------------------------------------
__global__ void conv_kv_kernel(const float* __restrict__ QKV,
                               const float* __restrict__ cosb,
                               const float* __restrict__ sinb,
                               __nv_bfloat16* __restrict__ Khi,
                               __nv_bfloat16* __restrict__ Klo,
                               __nv_bfloat16* __restrict__ Vhi,
                               __nv_bfloat16* __restrict__ Vlo)
{
    int idx = blockIdx.x * blockDim.x + threadIdx.x;
    if (idx >= ROWS * KVHEADS * 2) return;
    int half = idx & 1;
    int kvh  = (idx >> 1) % KVHEADS;
    int row  = idx / (2 * KVHEADS);
    int s    = row & (SEQ - 1);
    int b    = row >> 11;

    const float* kp = QKV + (size_t)row * NQKV + DMODEL + kvh * HDIM + half * 32;
    const float* vp = QKV + (size_t)row * NQKV + DMODEL + KVDIM + kvh * HDIM + half * 32;
    size_t drow = ((size_t)(b * KVHEADS + kvh) * SEQ + s) * HDIM + half * 32;

    float kv[32], vv[32];
#pragma unroll
    for (int i = 0; i < 8; ++i) {
        float4 a = *(const float4*)(kp + 4 * i);
        kv[4 * i] = a.x; kv[4 * i + 1] = a.y; kv[4 * i + 2] = a.z; kv[4 * i + 3] = a.w;
        float4 c = *(const float4*)(vp + 4 * i);
        vv[4 * i] = c.x; vv[4 * i + 1] = c.y; vv[4 * i + 2] = c.z; vv[4 * i + 3] = c.w;
    }
    if (half == 0) {   // rope the first 32 dims
#pragma unroll
        for (int d = 0; d < 16; ++d) {
            float c  = cosb[s * ROT + d];
            float sn = sinb[s * ROT + d];
            float xr = kv[d], xi = kv[d + 16];
            kv[d]      = xr * c - xi * sn;
            kv[d + 16] = xi * c + xr * sn;
        }
    }
    union { __nv_bfloat16 h[32]; uint4 u[4]; } KH, KL, VH, VL;
#pragma unroll
    for (int i = 0; i < 32; ++i) {
        KH.h[i] = __float2bfloat16_rn(kv[i]);
        KL.h[i] = __float2bfloat16_rn(kv[i] - __bfloat162float(KH.h[i]));
        VH.h[i] = __float2bfloat16_rn(vv[i]);
        VL.h[i] = __float2bfloat16_rn(vv[i] - __bfloat162float(VH.h[i]));
    }
#pragma unroll
    for (int i = 0; i < 4; ++i) {
        *(uint4*)(Khi + drow + 8 * i) = KH.u[i];
        *(uint4*)(Klo + drow + 8 * i) = KL.u[i];
        *(uint4*)(Vhi + drow + 8 * i) = VH.u[i];
        *(uint4*)(Vlo + drow + 8 * i) = VL.u[i];
    }
}

// ---------------------------------------------------------------------------
// Tensor-core flash attention; KV pre-split in gmem, staged via cp.async.
// Output written directly as split A3 ([hi|lo|hi], stride K3).
// ---------------------------------------------------------------------------
#define ATTN_SMEM 65536

__global__ __launch_bounds__(256)
void attn_mma(const float* __restrict__ QKV,
              const __nv_bfloat16* __restrict__ Khi,
              const __nv_bfloat16* __restrict__ Klo,
              const __nv_bfloat16* __restrict__ Vhi,
              const __nv_bfloat16* __restrict__ Vlo,
              __nv_bfloat16* __restrict__ A3)
{
    extern __shared__ char sm[];
    char* sKhi = sm;
    char* sKlo = sm + 16384;
    char* sVhi = sm + 32768;
    char* sVlo = sm + 49152;
    const uint32_t bKhi = smem_u32(sKhi);
    const uint32_t bKlo = smem_u32(sKlo);
    const uint32_t bVhi = smem_u32(sVhi);
    const uint32_t bVlo = smem_u32(sVlo);

    const int t   = threadIdx.x;
    const int wid = t >> 5;
    const int l   = t & 31;
    const int bh  = blockIdx.y;
    const int b   = bh / NHEADS;
    const int h   = bh % NHEADS;
    const int kvh = h >> 2;
    const int q0  = blockIdx.x * 128;

    // ---- stage Q (scaled 1/8, split) into sKhi/sKlo ----
    {
        const float* Qb = QKV + ((size_t)(b * SEQ + q0)) * NQKV + h * HDIM;
        for (int i = t; i < 128 * 16; i += 256) {
            int r  = i >> 4;
            int c4 = (i & 15) << 2;
            float4 v = *(const float4*)(Qb + (size_t)r * NQKV + c4);
            float x[4] = {v.x * 0.125f, v.y * 0.125f, v.z * 0.125f, v.w * 0.125f};
            union { __nv_bfloat16 hh[4]; uint2 u; } H, L;
#pragma unroll
            for (int j = 0; j < 4; ++j) {
                H.hh[j] = __float2bfloat16_rn(x[j]);
                L.hh[j] = __float2bfloat16_rn(x[j] - __bfloat162float(H.hh[j]));
            }
            uint32_t off = swz128((uint32_t)(r * 128 + c4 * 2));
            *(uint2*)(sKhi + off) = H.u;
            *(uint2*)(sKlo + off) = L.u;
        }
    }
    __syncthreads();

    uint32_t qhiF[4][4], qloF[4][4];
    {
        const int arw = wid * 16 + (l & 7) + ((l >> 3) & 1) * 8;
        const int ac  = ((l >> 4) & 1) * 16;
#pragma unroll
        for (int ks = 0; ks < 4; ++ks) {
            uint32_t off = swz128((uint32_t)(arw * 128 + ks * 32 + ac));
            LDSM4(qhiF[ks][0], qhiF[ks][1], qhiF[ks][2], qhiF[ks][3], bKhi + off);
            LDSM4(qloF[ks][0], qloF[ks][1], qloF[ks][2], qloF[ks][3], bKlo + off);
        }
    }
    __syncthreads();

    float oacc[8][4];
#pragma unroll
    for (int nt = 0; nt < 8; ++nt)
#pragma unroll
        for (int r = 0; r < 4; ++r) oacc[nt][r] = 0.f;
    float m0 = -1e30f, m1 = -1e30f;
    float l0 = 0.f, l1 = 0.f;

    const size_t kvbase = (size_t)(b * KVHEADS + kvh) * SEQ;

    for (int j0 = 0; j0 < SEQ; j0 += 128) {
        // ---- stage KV chunk: pure 16B async copies ----
        {
            const size_t g0 = (kvbase + j0) * HDIM;
            for (int i = t; i < 1024; i += 256) {
                int r  = i >> 3;
                int c8 = i & 7;
                size_t go = g0 + (size_t)r * HDIM + c8 * 8;
                uint32_t off = swz128((uint32_t)(r * 128 + c8 * 16));
                CPASYNC16(bKhi + off, Khi + go);
                CPASYNC16(bKlo + off, Klo + go);
                CPASYNC16(bVhi + off, Vhi + go);
                CPASYNC16(bVlo + off, Vlo + go);
            }
            CPASYNC_FENCE();
        }
        __syncthreads();

        // ---- S = Q'K'^T (3-term split) ----
        float sacc[16][4];
#pragma unroll
        for (int nt = 0; nt < 16; ++nt)
#pragma unroll
            for (int r = 0; r < 4; ++r) sacc[nt][r] = 0.f;

        {
            const int brw = (l & 7) + ((l >> 4) & 1) * 8;
            const int bc  = ((l >> 3) & 1) * 16;
#pragma unroll
            for (int ks = 0; ks < 4; ++ks) {
#pragma unroll
                for (int np = 0; np < 8; ++np) {
                    uint32_t off = swz128((uint32_t)((np * 16 + brw) * 128 + ks * 32 + bc));
                    uint32_t bh0, bh1, bh2, bh3, bl0, bl1, bl2, bl3;
                    LDSM4(bh0, bh1, bh2, bh3, bKhi + off);
                    LDSM4(bl0, bl1, bl2, bl3, bKlo + off);
                    mma16816(sacc[2 * np],     qhiF[ks], bh0, bh1);
                    mma16816(sacc[2 * np + 1], qhiF[ks], bh2, bh3);
                    mma16816(sacc[2 * np],     qloF[ks], bh0, bh1);
                    mma16816(sacc[2 * np + 1], qloF[ks], bh2, bh3);
                    mma16816(sacc[2 * np],     qhiF[ks], bl0, bl1);
                    mma16816(sacc[2 * np + 1], qhiF[ks], bl2, bl3);
                }
            }
        }

        // ---- online softmax ----
        float mx0 = -1e30f, mx1 = -1e30f;
#pragma unroll
        for (int nt = 0; nt < 16; ++nt) {
            mx0 = fmaxf(mx0, fmaxf(sacc[nt][0], sacc[nt][1]));
            mx1 = fmaxf(mx1, fmaxf(sacc[nt][2], sacc[nt][3]));
        }
        mx0 = fmaxf(mx0, __shfl_xor_sync(0xffffffff, mx0, 1));
        mx0 = fmaxf(mx0, __shfl_xor_sync(0xffffffff, mx0, 2));
        mx1 = fmaxf(mx1, __shfl_xor_sync(0xffffffff, mx1, 1));
        mx1 = fmaxf(mx1, __shfl_xor_sync(0xffffffff, mx1, 2));

        float mn0 = fmaxf(m0, mx0), mn1 = fmaxf(m1, mx1);
        float cr0 = __expf(m0 - mn0), cr1 = __expf(m1 - mn1);
        m0 = mn0; m1 = mn1;
        l0 *= cr0; l1 *= cr1;
#pragma unroll
        for (int nt = 0; nt < 8; ++nt) {
            oacc[nt][0] *= cr0; oacc[nt][1] *= cr0;
            oacc[nt][2] *= cr1; oacc[nt][3] *= cr1;
        }

#pragma unroll
        for (int nt = 0; nt < 16; ++nt) {
            sacc[nt][0] = __expf(sacc[nt][0] - mn0);
            sacc[nt][1] = __expf(sacc[nt][1] - mn0);
            sacc[nt][2] = __expf(sacc[nt][2] - mn1);
            sacc[nt][3] = __expf(sacc[nt][3] - mn1);
            l0 += sacc[nt][0] + sacc[nt][1];
            l1 += sacc[nt][2] + sacc[nt][3];
        }

        // ---- O += P V (3-term split) ----
        {
            const int vrw = (l & 7) + ((l >> 3) & 1) * 8;
            const int vc  = ((l >> 4) & 1) * 16;
#pragma unroll
            for (int kt = 0; kt < 8; ++kt) {
                float* sa = sacc[2 * kt];
                float* sb = sacc[2 * kt + 1];
                uint32_t ahi[4], alo[4];
                ahi[0] = packbf2(sa[0], sa[1]);
                ahi[1] = packbf2(sa[2], sa[3]);
                ahi[2] = packbf2(sb[0], sb[1]);
                ahi[3] = packbf2(sb[2], sb[3]);
                {
                    __nv_bfloat162 h0 = *(__nv_bfloat162*)&ahi[0];
                    __nv_bfloat162 h1 = *(__nv_bfloat162*)&ahi[1];
                    __nv_bfloat162 h2 = *(__nv_bfloat162*)&ahi[2];
                    __nv_bfloat162 h3 = *(__nv_bfloat162*)&ahi[3];
                    alo[0] = packbf2(sa[0] - __bfloat162float(h0.x), sa[1] - __bfloat162float(h0.y));
                    alo[1] = packbf2(sa[2] - __bfloat162float(h1.x), sa[3] - __bfloat162float(h1.y));
                    alo[2] = packbf2(sb[0] - __bfloat162float(h2.x), sb[1] - __bfloat162float(h2.y));
                    alo[3] = packbf2(sb[2] - __bfloat162float(h3.x), sb[3] - __bfloat162float(h3.y));
                }
#pragma unroll
                for (int vp = 0; vp < 4; ++vp) {
                    uint32_t off = swz128((uint32_t)((kt * 16 + vrw) * 128 + vp * 32 + vc));
                    uint32_t vh0, vh1, vh2, vh3, vl0, vl1, vl2, vl3;
                    LDSM4T(vh0, vh1, vh2, vh3, bVhi + off);
                    LDSM4T(vl0, vl1, vl2, vl3, bVlo + off);
                    mma16816(oacc[2 * vp],     ahi, vh0, vh1);
                    mma16816(oacc[2 * vp + 1], ahi, vh2, vh3);
                    mma16816(oacc[2 * vp],     alo, vh0, vh1);
                    mma16816(oacc[2 * vp + 1], alo, vh2, vh3);
                    mma16816(oacc[2 * vp],     ahi, vl0, vl1);
                    mma16816(oacc[2 * vp + 1], ahi, vl2, vl3);
                }
            }
        }
        __syncthreads();
    }

    // ---- finalize: write split A3 directly ----
    l0 += __shfl_xor_sync(0xffffffff, l0, 1);
    l0 += __shfl_xor_sync(0xffffffff, l0, 2);
    l1 += __shfl_xor_sync(0xffffffff, l1, 1);
    l1 += __shfl_xor_sync(0xffffffff, l1, 2);
    float inv0 = 1.f / l0, inv1 = 1.f / l1;

    const int row0 = b * SEQ + q0 + wid * 16 + (l >> 2);
    const int colb = h * HDIM + 2 * (l & 3);
#pragma unroll
    for (int nt = 0; nt < 8; ++nt) {
        int cc = colb + nt * 8;
#pragma unroll
        for (int half = 0; half < 2; ++half) {
            float vx = oacc[nt][2 * half]     * (half ? inv1 : inv0);
            float vy = oacc[nt][2 * half + 1] * (half ? inv1 : inv0);
            uint32_t H = packbf2(vx, vy);
            __nv_bfloat162 hh = *(__nv_bfloat162*)&H;
            uint32_t L = packbf2(vx - __bfloat162float(hh.x),
                                 vy - __bfloat162float(hh.y));
            size_t base = (size_t)(row0 + half * 8) * K3 + cc;
            *(uint32_t*)(A3 + base)              = H;
            *(uint32_t*)(A3 + base + DMODEL)     = L;
            *(uint32_t*)(A3 + base + 2 * DMODEL) = H;
        }
    }
}

// ---------------------------------------------------------------------------
extern "C" void kernel_launch(void* const* d_in, const int* in_sizes, int n_in,
                              void* d_out, int out_size)
{
    const float* hidden = (const float*)d_in[0];
    const float* cosb   = (const float*)d_in[1];
    const float* sinb   = (const float*)d_in[2];
    const float* Wq     = (const float*)d_in[3];
    const float* Wk     = (const float*)d_in[4];
    const float* Wv     = (const float*)d_in[5];
    const float* Wo     = (const float*)d_in[6];
    const float* bo     = (const float*)d_in[7];
    float* out          = (float*)d_out;

    float* QKV;
    __nv_bfloat16 *A3, *Bqkv, *Bo, *Khi, *Klo, *Vhi, *Vlo;
    cudaGetSymbolAddress((void**)&QKV,  g_QKV);
    cudaGetSymbolAddress((void**)&A3,   g_A3);
    cudaGetSymbolAddress((void**)&Bqkv, g_Bqkv);
    cudaGetSymbolAddress((void**)&Bo,   g_Bo);
    cudaGetSymbolAddress((void**)&Khi,  g_Khi);
    cudaGetSymbolAddress((void**)&Klo,  g_Klo);
    cudaGetSymbolAddress((void**)&Vhi,  g_Vhi);
    cudaGetSymbolAddress((void**)&Vlo,  g_Vlo);

    // Split conversions (weights packed into one fused buffer)
    {
        int tot = ROWS * DMODEL;
        convA_kernel<<<(tot / 4 + 255) / 256, 256>>>(hidden, A3, tot);
        convW_kernel<<<dim3(DMODEL / 32, DMODEL / 32), dim3(32, 8)>>>(
            Wq, Bqkv, DMODEL);
        convW_kernel<<<dim3(KVDIM  / 32, DMODEL / 32), dim3(32, 8)>>>(
            Wk, Bqkv + (size_t)DMODEL * K3, KVDIM);
        convW_kernel<<<dim3(KVDIM  / 32, DMODEL / 32), dim3(32, 8)>>>(
            Wv, Bqkv + (size_t)(DMODEL + KVDIM) * K3, KVDIM);
        convW_kernel<<<dim3(DMODEL / 32, DMODEL / 32), dim3(32, 8)>>>(
            Wo, Bo, DMODEL);    // FIXED: was g_Bo (host shadow, ATS-absorbed)
    }

    // Fused QKV projection
    hmma_gemm<false><<<dim3(NQKV / 128, ROWS / 128), 256>>>(
        A3, Bqkv, QKV, NQKV, nullptr, nullptr);

    // RoPE Q (in fused buffer) + KV rope/split/pack
    {
        int totq = ROWS * NHEADS * 16;
        ropeQ_kernel<<<(totq + 255) / 256, 256>>>(QKV, cosb, sinb, totq);
        int totkv = ROWS * KVHEADS * 2;
        conv_kv_kernel<<<(totkv + 255) / 256, 256>>>(QKV, cosb, sinb,
                                                     Khi, Klo, Vhi, Vlo);
    }

    // Attention (writes split A3 directly)
    {
        cudaFuncSetAttribute(attn_mma,
                             cudaFuncAttributeMaxDynamicSharedMemorySize, ATTN_SMEM);
        attn_mma<<<dim3(SEQ / 128, B_SZ * NHEADS), 256, ATTN_SMEM>>>(
            QKV, Khi, Klo, Vhi, Vlo, A3);
    }

    // Output projection + bias + residual
    hmma_gemm<true><<<dim3(DMODEL / 128, ROWS / 128), 256>>>(
        A3, Bo, out, DMODEL, bo, hidden);
}